// round 8
// baseline (speedup 1.0000x reference)
#include <cuda_runtime.h>
#include <cuda_bf16.h>
#include <cstdint>

// Problem constants
#define Bz   2
#define SEQ  2048
#define CC   768
#define HH   12
#define DH   64
#define MM   (Bz*SEQ)        // 4096
#define C3   (3*CC)          // 2304

// Scratch (no cudaMalloc allowed)
__device__ float g_qkv[(size_t)MM * C3];   // [B*N, 3*C]; reused as proj partials
__device__ float g_att[(size_t)MM * CC];   // attention output [B*N, C]
__device__ float g_xr [(size_t)MM * CC];   // tf32-rounded x
__device__ float g_w  [(size_t)CC * C3];   // tf32-rounded weights (reused)
__device__ float g_p0 [(size_t)MM * CC];   // flash partial O, kv-half 0
__device__ float g_p1 [(size_t)MM * CC];   // flash partial O, kv-half 1
__device__ float2 g_ml[2 * Bz * HH * SEQ]; // per (z,b,h,row): {m, l}

__device__ __forceinline__ float tf32r(float x) {
    float o;
    asm("cvt.rna.tf32.f32 %0, %1;" : "=f"(o) : "f"(x));
    return o;
}
__device__ __forceinline__ uint32_t tf32u(float x) {
    float o;
    asm("cvt.rna.tf32.f32 %0, %1;" : "=f"(o) : "f"(x));
    return __float_as_uint(o);
}

#define MMA_TF32(d, a, b)                                                     \
    asm volatile("mma.sync.aligned.m16n8k8.row.col.f32.tf32.tf32.f32 "        \
        "{%0,%1,%2,%3}, {%4,%5,%6,%7}, {%8,%9}, {%0,%1,%2,%3};"               \
        : "+f"((d)[0]), "+f"((d)[1]), "+f"((d)[2]), "+f"((d)[3])              \
        : "r"((a)[0]), "r"((a)[1]), "r"((a)[2]), "r"((a)[3]),                 \
          "r"((b)[0]), "r"((b)[1]))

// ---------------------------------------------------------------------------
// Streaming tf32 rounding
// ---------------------------------------------------------------------------
__global__ __launch_bounds__(256) void round_tf32(
    const float* __restrict__ src, float* __restrict__ dst, int n4)
{
    const int i = blockIdx.x * blockDim.x + threadIdx.x;
    if (i < n4) {
        float4 v = *(const float4*)(src + 4 * (size_t)i);
        v.x = tf32r(v.x); v.y = tf32r(v.y);
        v.z = tf32r(v.z); v.w = tf32r(v.w);
        *(float4*)(dst + 4 * (size_t)i) = v;
    }
}

// ---------------------------------------------------------------------------
// tf32 mma.sync GEMM, cp.async 3-stage. Pre-rounded inputs.
// Computes C = A[:, k0:k0+klen] * Bw[k0:k0+klen, :] (+bias if bias != null).
// A row stride = Kld.  round_out rounds stored output to tf32.
// ---------------------------------------------------------------------------
#define AS_LD   36
#define BS_LD   136
#define BUF_F   (128*AS_LD + 32*BS_LD)      // 8960 floats
#define GEMM_SMEM (3 * BUF_F * 4)           // 107520 bytes

__global__ __launch_bounds__(256, 2) void gemm_mma(
    const float* __restrict__ A, const float* __restrict__ Bw,
    const float* __restrict__ bias, float* __restrict__ Cm,
    int Nn, int Kld, int k0, int klen, int round_out)
{
    extern __shared__ float smem[];
    uint32_t smb;
    asm("{ .reg .u64 t; cvta.to.shared.u64 t, %1; cvt.u32.u64 %0, t; }"
        : "=r"(smb) : "l"(smem));
    const int tid = threadIdx.x;
    const int wid = tid >> 5;
    const int lane = tid & 31;
    const int g  = lane >> 2;
    const int tg = lane & 3;
    const int wr = wid >> 2;
    const int wc = wid & 3;
    const int row0 = blockIdx.y * 128, col0 = blockIdx.x * 128;

    const int aRowB = tid >> 3;
    const int aCol4 = tid & 7;
    const int bRowB = tid >> 5;
    const int bCol4 = tid & 31;

    float acc[4][4][4];
    #pragma unroll
    for (int mt = 0; mt < 4; mt++)
        #pragma unroll
        for (int nt = 0; nt < 4; nt++)
            #pragma unroll
            for (int r = 0; r < 4; r++) acc[mt][nt][r] = 0.f;

    const int chunks = klen / 32;

#define GISSUE(cc, pp) do {                                                   \
    const int kb_ = k0 + (cc) * 32;                                           \
    _Pragma("unroll")                                                         \
    for (int i_ = 0; i_ < 4; i_++) {                                          \
        const float* as_ = A + (size_t)(row0 + aRowB + 32 * i_) * Kld + kb_ + aCol4 * 4; \
        const uint32_t ad_ = smb + (uint32_t)((pp) * BUF_F + (aRowB + 32 * i_) * AS_LD + aCol4 * 4) * 4u; \
        asm volatile("cp.async.cg.shared.global [%0], [%1], 16;" :: "r"(ad_), "l"(as_)); \
        const float* bs_ = Bw + (size_t)(kb_ + bRowB + 8 * i_) * Nn + col0 + bCol4 * 4; \
        const uint32_t bd_ = smb + (uint32_t)((pp) * BUF_F + 128 * AS_LD + (bRowB + 8 * i_) * BS_LD + bCol4 * 4) * 4u; \
        asm volatile("cp.async.cg.shared.global [%0], [%1], 16;" :: "r"(bd_), "l"(bs_)); \
    }                                                                         \
    asm volatile("cp.async.commit_group;");                                   \
} while (0)

    GISSUE(0, 0);
    GISSUE(1, 1);

    for (int c = 0; c < chunks; c++) {
        if (c + 1 < chunks) {
            asm volatile("cp.async.wait_group 1;" ::: "memory");
        } else {
            asm volatile("cp.async.wait_group 0;" ::: "memory");
        }
        __syncthreads();
        if (c + 2 < chunks) GISSUE(c + 2, (c + 2) % 3);

        const float* As = smem + (c % 3) * BUF_F;
        const float* Bs = As + 128 * AS_LD;
        #pragma unroll
        for (int kk = 0; kk < 32; kk += 8) {
            uint32_t af[4][4], bf[4][2];
            #pragma unroll
            for (int mt = 0; mt < 4; mt++) {
                const int m = wr * 64 + mt * 16 + g;
                af[mt][0] = __float_as_uint(As[m * AS_LD + kk + tg]);
                af[mt][1] = __float_as_uint(As[(m + 8) * AS_LD + kk + tg]);
                af[mt][2] = __float_as_uint(As[m * AS_LD + kk + tg + 4]);
                af[mt][3] = __float_as_uint(As[(m + 8) * AS_LD + kk + tg + 4]);
            }
            #pragma unroll
            for (int nt = 0; nt < 4; nt++) {
                const int n = wc * 32 + nt * 8 + g;
                bf[nt][0] = __float_as_uint(Bs[(kk + tg) * BS_LD + n]);
                bf[nt][1] = __float_as_uint(Bs[(kk + tg + 4) * BS_LD + n]);
            }
            #pragma unroll
            for (int mt = 0; mt < 4; mt++)
                #pragma unroll
                for (int nt = 0; nt < 4; nt++)
                    MMA_TF32(acc[mt][nt], af[mt], bf[nt]);
        }
    }

    #pragma unroll
    for (int mt = 0; mt < 4; mt++) {
        const int r0 = row0 + wr * 64 + mt * 16 + g;
        #pragma unroll
        for (int nt = 0; nt < 4; nt++) {
            const int cc = col0 + wc * 32 + nt * 8 + 2 * tg;
            float b0 = 0.f, b1 = 0.f;
            if (bias) { b0 = __ldg(bias + cc); b1 = __ldg(bias + cc + 1); }
            float2 v0, v1;
            v0.x = acc[mt][nt][0] + b0; v0.y = acc[mt][nt][1] + b1;
            v1.x = acc[mt][nt][2] + b0; v1.y = acc[mt][nt][3] + b1;
            if (round_out) {
                v0.x = tf32r(v0.x); v0.y = tf32r(v0.y);
                v1.x = tf32r(v1.x); v1.y = tf32r(v1.y);
            }
            *(float2*)(Cm + (size_t)r0 * Nn + cc) = v0;
            *(float2*)(Cm + (size_t)(r0 + 8) * Nn + cc) = v1;
        }
    }
}

// ---------------------------------------------------------------------------
// proj split-K combine: out = p0 + p1 + p2 + bias
// ---------------------------------------------------------------------------
__global__ __launch_bounds__(256) void proj_combine(
    const float* __restrict__ parts, const float* __restrict__ bias,
    float* __restrict__ out)
{
    const int i = blockIdx.x * blockDim.x + threadIdx.x;
    if (i >= MM * CC / 4) return;
    const size_t off = 4 * (size_t)i;
    float4 a = *(const float4*)(parts + off);
    float4 b = *(const float4*)(parts + (size_t)MM * CC + off);
    float4 c = *(const float4*)(parts + 2 * (size_t)MM * CC + off);
    const int col = (int)(off % CC);
    float4 bb = *(const float4*)(bias + col);
    float4 r;
    r.x = a.x + b.x + c.x + bb.x;
    r.y = a.y + b.y + c.y + bb.y;
    r.z = a.z + b.z + c.z + bb.z;
    r.w = a.w + b.w + c.w + bb.w;
    *(float4*)(out + off) = r;
}

// ---------------------------------------------------------------------------
// Fused RMSNorm + RoPE; outputs tf32-rounded.
// ---------------------------------------------------------------------------
__global__ __launch_bounds__(256) void rmsnorm_rope(
    const float* __restrict__ cosb, const float* __restrict__ sinb,
    const float* __restrict__ qn_w, const float* __restrict__ kn_w)
{
    const int warp = (blockIdx.x * blockDim.x + threadIdx.x) >> 5;
    const int lane = threadIdx.x & 31;
    const int which = warp & 1;
    const int h     = (warp >> 1) % HH;
    const int bn    = warp / (2 * HH);
    const int n     = bn & (SEQ - 1);

    const float* w = which ? kn_w : qn_w;
    float* p = g_qkv + (size_t)bn * C3 + which * CC + h * DH;

    float2 v = *(float2*)(p + 2 * lane);
    float ss = v.x * v.x + v.y * v.y;
    #pragma unroll
    for (int o = 16; o; o >>= 1) ss += __shfl_xor_sync(0xffffffffu, ss, o);
    const float inv = rsqrtf(ss * (1.0f / (float)DH) + 1e-6f);

    float x0 = v.x * inv * w[2 * lane];
    float x1 = v.y * inv * w[2 * lane + 1];
    const float c = cosb[n * (DH / 2) + lane];
    const float s = sinb[n * (DH / 2) + lane];
    float2 r;
    r.x = tf32r(x0 * c - x1 * s);
    r.y = tf32r(x0 * s + x1 * c);
    *(float2*)(p + 2 * lane) = r;
}

// ---------------------------------------------------------------------------
// Flash attention, split-KV: blockIdx.z selects keys [z*1024, z*1024+1024).
// Writes unnormalized partial O and per-row {m, l}.
// ---------------------------------------------------------------------------
#define KS_LD 68
#define VS_LD 72
#define ATT_SMEM (17920 * 4)              // 71680 bytes
#define QSCALE   (0.125f * 1.44269504f)   // Dh^-0.5 * log2(e)
#define KV_HALF  (SEQ / 2)                // 1024 keys per z

__global__ __launch_bounds__(256, 2) void flash_mma()
{
    extern __shared__ float sm[];
    const int tid = threadIdx.x;
    const int lane = tid & 31, wid = tid >> 5;
    const int g = lane >> 2, tg = lane & 3;
    const int b = blockIdx.x / HH, h = blockIdx.x % HH;
    const int q0 = blockIdx.y * 128;
    const int z = blockIdx.z;
    const float* base = g_qkv + (size_t)b * SEQ * C3;
    const float* kvb = base + (size_t)(z * KV_HALF) * C3 + CC + h * DH;

    uint32_t smb;
    asm("{ .reg .u64 t; cvta.to.shared.u64 t, %1; cvt.u32.u64 %0, t; }"
        : "=r"(smb) : "l"(sm));

    // ---- stage Q (prescaled, tf32) ----
    {
        const float* Qg = base + (size_t)q0 * C3 + h * DH;
        #pragma unroll
        for (int i = 0; i < 8; i++) {
            const int idx = tid + i * 256;
            const int r = idx >> 4, c = (idx & 15) * 4;
            float4 v = *(const float4*)(Qg + (size_t)r * C3 + c);
            float* d = sm + r * KS_LD + c;
            d[0] = tf32r(QSCALE * v.x);
            d[1] = tf32r(QSCALE * v.y);
            d[2] = tf32r(QSCALE * v.z);
            d[3] = tf32r(QSCALE * v.w);
        }
    }
    __syncthreads();
    uint32_t qf[8][4];
    {
        const float* Qs = sm + (wid * 16) * KS_LD;
        #pragma unroll
        for (int kk = 0; kk < 8; kk++) {
            qf[kk][0] = __float_as_uint(Qs[g * KS_LD + kk * 8 + tg]);
            qf[kk][1] = __float_as_uint(Qs[(g + 8) * KS_LD + kk * 8 + tg]);
            qf[kk][2] = __float_as_uint(Qs[g * KS_LD + kk * 8 + tg + 4]);
            qf[kk][3] = __float_as_uint(Qs[(g + 8) * KS_LD + kk * 8 + tg + 4]);
        }
    }
    __syncthreads();

    const int pr = tid >> 2;
    const int pc = (tid & 3) * 16;

#define AISSUE(itt, pp) do {                                                  \
    const float* src_ = kvb + (size_t)((itt) * 64 + pr) * C3 + pc;            \
    const uint32_t kd_ = smb + (uint32_t)((pp) * 4352 + pr * KS_LD + pc) * 4u;\
    const uint32_t vd_ = smb + (uint32_t)(8704 + (pp) * 4608 + pr * VS_LD + pc) * 4u; \
    _Pragma("unroll")                                                         \
    for (int j_ = 0; j_ < 4; j_++) {                                          \
        asm volatile("cp.async.cg.shared.global [%0], [%1], 16;"              \
                     :: "r"(kd_ + j_ * 16), "l"(src_ + j_ * 4));              \
        asm volatile("cp.async.cg.shared.global [%0], [%1], 16;"              \
                     :: "r"(vd_ + j_ * 16), "l"(src_ + CC + j_ * 4));         \
    }                                                                         \
    asm volatile("cp.async.commit_group;");                                   \
} while (0)

    AISSUE(0, 0);

    float O[8][4];
    #pragma unroll
    for (int u = 0; u < 8; u++) { O[u][0] = O[u][1] = O[u][2] = O[u][3] = 0.f; }
    float m0 = -1e30f, m1 = -1e30f, l0 = 0.f, l1 = 0.f;

    const int sA = (lane & ~3) | (tg >> 1);
    const bool odd = (tg & 1);

    for (int it = 0; it < KV_HALF / 64; it++) {
        const int p = it & 1;
        asm volatile("cp.async.wait_group 0;" ::: "memory");
        __syncthreads();
        if (it + 1 < KV_HALF / 64) AISSUE(it + 1, p ^ 1);

        const float* Kb = sm + p * 4352;
        const float* Vb = sm + 8704 + p * 4608;

        float S[8][4];
        #pragma unroll
        for (int t = 0; t < 8; t++) {
            S[t][0] = S[t][1] = S[t][2] = S[t][3] = 0.f;
            const float* kr = Kb + (t * 8 + g) * KS_LD;
            #pragma unroll
            for (int kk = 0; kk < 8; kk++) {
                uint32_t bf[2];
                bf[0] = __float_as_uint(kr[kk * 8 + tg]);
                bf[1] = __float_as_uint(kr[kk * 8 + tg + 4]);
                MMA_TF32(S[t], qf[kk], bf);
            }
        }
        float mx0 = -1e30f, mx1 = -1e30f;
        #pragma unroll
        for (int t = 0; t < 8; t++) {
            mx0 = fmaxf(mx0, fmaxf(S[t][0], S[t][1]));
            mx1 = fmaxf(mx1, fmaxf(S[t][2], S[t][3]));
        }
        mx0 = fmaxf(mx0, __shfl_xor_sync(0xffffffffu, mx0, 1));
        mx0 = fmaxf(mx0, __shfl_xor_sync(0xffffffffu, mx0, 2));
        mx1 = fmaxf(mx1, __shfl_xor_sync(0xffffffffu, mx1, 1));
        mx1 = fmaxf(mx1, __shfl_xor_sync(0xffffffffu, mx1, 2));
        const float n0 = fmaxf(m0, mx0), n1 = fmaxf(m1, mx1);
        const float c0 = exp2f(m0 - n0), c1 = exp2f(m1 - n1);
        m0 = n0; m1 = n1;
        #pragma unroll
        for (int u = 0; u < 8; u++) {
            O[u][0] *= c0; O[u][1] *= c0; O[u][2] *= c1; O[u][3] *= c1;
        }
        float s0 = 0.f, s1 = 0.f;
        #pragma unroll
        for (int t = 0; t < 8; t++) {
            const float e0 = exp2f(S[t][0] - n0), e1 = exp2f(S[t][1] - n0);
            const float e2 = exp2f(S[t][2] - n1), e3 = exp2f(S[t][3] - n1);
            s0 += e0 + e1; s1 += e2 + e3;
            const uint32_t p0 = tf32u(e0), p1 = tf32u(e1);
            const uint32_t p2 = tf32u(e2), p3 = tf32u(e3);
            const uint32_t x0 = __shfl_sync(0xffffffffu, p0, sA);
            const uint32_t x1 = __shfl_sync(0xffffffffu, p1, sA);
            const uint32_t x2 = __shfl_sync(0xffffffffu, p2, sA);
            const uint32_t x3 = __shfl_sync(0xffffffffu, p3, sA);
            const uint32_t y0 = __shfl_sync(0xffffffffu, p0, sA + 2);
            const uint32_t y1 = __shfl_sync(0xffffffffu, p1, sA + 2);
            const uint32_t y2 = __shfl_sync(0xffffffffu, p2, sA + 2);
            const uint32_t y3 = __shfl_sync(0xffffffffu, p3, sA + 2);
            uint32_t af[4];
            af[0] = odd ? x1 : x0;
            af[1] = odd ? x3 : x2;
            af[2] = odd ? y1 : y0;
            af[3] = odd ? y3 : y2;
            const float* vr0 = Vb + (t * 8 + tg) * VS_LD;
            const float* vr1 = Vb + (t * 8 + tg + 4) * VS_LD;
            #pragma unroll
            for (int u = 0; u < 8; u++) {
                uint32_t bf[2];
                bf[0] = __float_as_uint(vr0[u * 8 + g]);
                bf[1] = __float_as_uint(vr1[u * 8 + g]);
                MMA_TF32(O[u], af, bf);
            }
        }
        l0 = l0 * c0 + s0; l1 = l1 * c1 + s1;
    }

    // epilogue: reduce l across quad, store raw partial O + {m,l}
    l0 += __shfl_xor_sync(0xffffffffu, l0, 1);
    l0 += __shfl_xor_sync(0xffffffffu, l0, 2);
    l1 += __shfl_xor_sync(0xffffffffu, l1, 1);
    l1 += __shfl_xor_sync(0xffffffffu, l1, 2);
    const int r0 = q0 + wid * 16 + g;
    float* pob = z ? g_p1 : g_p0;
    float* o0 = pob + (size_t)(b * SEQ + r0) * CC + h * DH;
    float* o1 = o0 + (size_t)8 * CC;
    #pragma unroll
    for (int u = 0; u < 8; u++) {
        float2 v0, v1;
        v0.x = O[u][0]; v0.y = O[u][1];
        v1.x = O[u][2]; v1.y = O[u][3];
        *(float2*)(o0 + u * 8 + 2 * tg) = v0;
        *(float2*)(o1 + u * 8 + 2 * tg) = v1;
    }
    if (tg == 0) {
        const int mlb = ((z * Bz + b) * HH + h) * SEQ;
        g_ml[mlb + r0]     = make_float2(m0, l0);
        g_ml[mlb + r0 + 8] = make_float2(m1, l1);
    }
}

// ---------------------------------------------------------------------------
// Split-KV combine: one warp per (b, row, h); merge halves, normalize,
// round to tf32 (feeds proj), store to g_att.
// ---------------------------------------------------------------------------
__global__ __launch_bounds__(256) void combine_attn()
{
    const int w = (blockIdx.x * blockDim.x + threadIdx.x) >> 5;
    const int lane = threadIdx.x & 31;
    const int h = w % HH;
    const int row = (w / HH) & (SEQ - 1);
    const int b = w / (HH * SEQ);

    const float2 ml0 = g_ml[((0 * Bz + b) * HH + h) * SEQ + row];
    const float2 ml1 = g_ml[((1 * Bz + b) * HH + h) * SEQ + row];
    const float ms = fmaxf(ml0.x, ml1.x);
    const float w0 = exp2f(ml0.x - ms), w1 = exp2f(ml1.x - ms);
    const float inv = 1.f / (ml0.y * w0 + ml1.y * w1);
    const float f0 = w0 * inv, f1 = w1 * inv;

    const size_t off = (size_t)(b * SEQ + row) * CC + h * DH + lane * 2;
    const float2 p0 = *(const float2*)(g_p0 + off);
    const float2 p1 = *(const float2*)(g_p1 + off);
    float2 r;
    r.x = tf32r(p0.x * f0 + p1.x * f1);
    r.y = tf32r(p0.y * f0 + p1.y * f1);
    *(float2*)(g_att + off) = r;
}

// ---------------------------------------------------------------------------
extern "C" void kernel_launch(void* const* d_in, const int* in_sizes, int n_in,
                              void* d_out, int out_size)
{
    const float* x      = (const float*)d_in[0];
    const float* cosb   = (const float*)d_in[1];
    const float* sinb   = (const float*)d_in[2];
    const float* qkv_w  = (const float*)d_in[3];
    const float* qkv_b  = (const float*)d_in[4];
    const float* proj_w = (const float*)d_in[5];
    const float* proj_b = (const float*)d_in[6];
    const float* qn_w   = (const float*)d_in[7];
    const float* kn_w   = (const float*)d_in[8];
    float* out = (float*)d_out;

    float* qkv; cudaGetSymbolAddress((void**)&qkv, g_qkv);
    float* att; cudaGetSymbolAddress((void**)&att, g_att);
    float* xr;  cudaGetSymbolAddress((void**)&xr,  g_xr);
    float* wbuf; cudaGetSymbolAddress((void**)&wbuf, g_w);

    static int smem_set = 0;
    if (!smem_set) {
        cudaFuncSetAttribute(gemm_mma, cudaFuncAttributeMaxDynamicSharedMemorySize,
                             GEMM_SMEM);
        cudaFuncSetAttribute(flash_mma, cudaFuncAttributeMaxDynamicSharedMemorySize,
                             ATT_SMEM);
        smem_set = 1;
    }

    // 0) pre-round inputs
    round_tf32<<<(MM * CC / 4 + 255) / 256, 256>>>(x, xr, MM * CC / 4);
    round_tf32<<<(CC * C3 / 4 + 255) / 256, 256>>>(qkv_w, wbuf, CC * C3 / 4);

    // 1) qkv = xr @ w + qkv_b (rounded output)
    {
        dim3 grid(C3 / 128, MM / 128);
        gemm_mma<<<grid, 256, GEMM_SMEM>>>(xr, wbuf, qkv_b, qkv, C3, CC, 0, CC, 1);
    }
    // 2) RMSNorm + RoPE on q,k (in place, rounded)
    {
        const int rows = 2 * MM * HH;
        rmsnorm_rope<<<rows / 8, 256>>>(cosb, sinb, qn_w, kn_w);
    }
    // 3) attention — split-KV 2-way + combine
    {
        dim3 grid(Bz * HH, SEQ / 128, 2);
        flash_mma<<<grid, 256, ATT_SMEM>>>();
        combine_attn<<<Bz * SEQ * HH / 8, 256>>>();
    }
    // 4) proj — split-K 3-way into g_qkv scratch, then combine with bias
    round_tf32<<<(CC * CC / 4 + 255) / 256, 256>>>(proj_w, wbuf, CC * CC / 4);
    {
        dim3 grid(CC / 128, MM / 128);
        for (int s = 0; s < 3; s++)
            gemm_mma<<<grid, 256, GEMM_SMEM>>>(att, wbuf, nullptr,
                                               qkv + (size_t)s * MM * CC,
                                               CC, CC, s * 256, 256, 0);
        proj_combine<<<(MM * CC / 4 + 255) / 256, 256>>>(qkv, proj_b, out);
    }
}